// round 11
// baseline (speedup 1.0000x reference)
#include <cuda_runtime.h>
#include <cuda_fp16.h>
#include <cstdint>

#define T_TOK 8192
#define DIMD  1024
#define HID   2816
#define NE    8

#define BM 128
#define BN 128
#define BK 32
#define LDT 40            // halves per smem row (80B pitch, 16B aligned, conflict-free)
#define STG_LD 132        // floats per staging row

#define TILE_H   (BM * LDT)            // 5120 halves per tile
#define STAGE1_H (3 * TILE_H)
#define STAGE2_H (2 * TILE_H)
#define SMEM1 (3 * STAGE1_H * 2)       // 92160 B
#define SMEM2 (128 * STG_LD * 4)       // 67584 B (>= pipeline 61440)

#define NK1 (DIMD / BK)   // 32
#define NK2 (HID / BK)    // 88

// ---------------- static scratch (allocation-free) ----------------
__device__ int    g_counts[NE];
__device__ int    g_list[NE * T_TOK];
__device__ int    g_me[2 * T_TOK];
__device__ int    g_mp[2 * T_TOK];
__device__ float  g_mw[2 * T_TOK];
__device__ __half g_xh  [(size_t)T_TOK * DIMD];
__device__ __half g_w1h [(size_t)NE * HID * DIMD];
__device__ __half g_w3h [(size_t)NE * HID * DIMD];
__device__ __half g_w2h [(size_t)NE * DIMD * HID];
__device__ __half g_sw1h[(size_t)HID * DIMD];
__device__ __half g_sw3h[(size_t)HID * DIMD];
__device__ __half g_sw2h[(size_t)DIMD * HID];
__device__ __half g_acth[(size_t)(NE + 1) * T_TOK * HID];
__device__ float  g_part[(size_t)(NE + 1) * T_TOK * DIMD];

// ---------------- helpers ----------------
__device__ __forceinline__ void cp16(uint32_t d, const void* s) {
    asm volatile("cp.async.ca.shared.global [%0], [%1], 16;\n" :: "r"(d), "l"(s));
}
#define CPCOMMIT() asm volatile("cp.async.commit_group;\n" ::: "memory")
#define CPWAIT1()  asm volatile("cp.async.wait_group 1;\n" ::: "memory")

__device__ __forceinline__ void ldsm4(uint32_t* r, uint32_t addr) {
    asm volatile("ldmatrix.sync.aligned.m8n8.x4.shared.b16 {%0,%1,%2,%3}, [%4];"
                 : "=r"(r[0]), "=r"(r[1]), "=r"(r[2]), "=r"(r[3]) : "r"(addr));
}
__device__ __forceinline__ void mma16816(float* c, const uint32_t* a, uint32_t b0, uint32_t b1) {
    asm volatile("mma.sync.aligned.m16n8k16.row.col.f32.f16.f16.f32 "
                 "{%0,%1,%2,%3}, {%4,%5,%6,%7}, {%8,%9}, {%0,%1,%2,%3};"
                 : "+f"(c[0]), "+f"(c[1]), "+f"(c[2]), "+f"(c[3])
                 : "r"(a[0]), "r"(a[1]), "r"(a[2]), "r"(a[3]), "r"(b0), "r"(b1));
}

// ============================================================================
// f32 -> f16 conversion pre-pass
// ============================================================================
__global__ __launch_bounds__(256) void tohalf_kernel(const float* __restrict__ src,
                                                     __half* __restrict__ dst, int n4)
{
    int i = blockIdx.x * 256 + threadIdx.x;
    if (i < n4) {
        float4 v = ((const float4*)src)[i];
        __half2 a = __floats2half2_rn(v.x, v.y);
        __half2 b = __floats2half2_rn(v.z, v.w);
        ((__half2*)dst)[2 * i]     = a;
        ((__half2*)dst)[2 * i + 1] = b;
    }
}

// ============================================================================
// Gate
// ============================================================================
__global__ __launch_bounds__(256) void gate_kernel(const float* __restrict__ x,
                                                   const float* __restrict__ gw)
{
    __shared__ float sgw[NE * DIMD];
    for (int i = threadIdx.x; i < NE * DIMD; i += 256) sgw[i] = gw[i];
    __syncthreads();

    int warp = threadIdx.x >> 5, lane = threadIdx.x & 31;
    int t = blockIdx.x * 8 + warp;
    const float* xp = x + (size_t)t * DIMD;

    float acc[NE];
#pragma unroll
    for (int e = 0; e < NE; e++) acc[e] = 0.f;
    for (int k = lane; k < DIMD; k += 32) {
        float xv = xp[k];
#pragma unroll
        for (int e = 0; e < NE; e++) acc[e] += xv * sgw[e * DIMD + k];
    }
#pragma unroll
    for (int e = 0; e < NE; e++)
#pragma unroll
        for (int o = 16; o > 0; o >>= 1) acc[e] += __shfl_xor_sync(0xffffffffu, acc[e], o);

    if (lane == 0) {
        int e0 = 0; float l0 = acc[0];
#pragma unroll
        for (int e = 1; e < NE; e++) if (acc[e] > l0) { l0 = acc[e]; e0 = e; }
        int e1 = (e0 == 0) ? 1 : 0; float l1 = acc[e1];
#pragma unroll
        for (int e = 0; e < NE; e++) if (e != e0 && acc[e] > l1) { l1 = acc[e]; e1 = e; }
        float w0 = 1.f / (1.f + __expf(l1 - l0));
        float w1 = 1.f - w0;
        int p0 = atomicAdd(&g_counts[e0], 1);
        g_list[e0 * T_TOK + p0] = t;
        int p1 = atomicAdd(&g_counts[e1], 1);
        g_list[e1 * T_TOK + p1] = t;
        g_me[2 * t] = e0; g_me[2 * t + 1] = e1;
        g_mp[2 * t] = p0; g_mp[2 * t + 1] = p1;
        g_mw[2 * t] = w0; g_mw[2 * t + 1] = w1;
    }
}

// ============================================================================
// GEMM1 (mma.sync fp16): act = silu(X W1^T) * (X W3^T)
// grid = (64, 22, 9); CTA 128x128 dual-B; warp 32x64
// ============================================================================
__global__ __launch_bounds__(256, 1) void gemm1_kernel()
{
    extern __shared__ char smem[];
    const int tid = threadIdx.x, wid = tid >> 5, lane = tid & 31;

    int seg = blockIdx.z;
    int count; const int* list; const __half* B1p; const __half* B3p;
    if (seg == 0) { count = T_TOK; list = nullptr; B1p = g_sw1h; B3p = g_sw3h; }
    else {
        int e = seg - 1;
        count = g_counts[e];
        list  = g_list + e * T_TOK;
        B1p = g_w1h + (size_t)e * HID * DIMD;
        B3p = g_w3h + (size_t)e * HID * DIMD;
    }
    int m0 = blockIdx.x * BM;
    if (m0 >= count) return;
    int n0 = blockIdx.y * BN;

    __half* sH = (__half*)smem;
    uint32_t sbase = (uint32_t)__cvta_generic_to_shared(sH);

    // cp.async map: 1536 16B-chunks / stage, 6 per thread
    const __half* srcp[6]; uint32_t dsto[6];
#pragma unroll
    for (int i = 0; i < 6; i++) {
        int q = tid + 256 * i;
        int tile = q >> 9;            // 0=A, 1=B1, 2=B3
        int r = (q >> 2) & 127;
        int c = q & 3;
        const __half* s;
        if (tile == 0) {
            int gr = m0 + r;
            int tok = (gr < count) ? (list ? list[gr] : gr) : 0;
            s = g_xh + (size_t)tok * DIMD + c * 8;
        } else if (tile == 1) s = B1p + (size_t)(n0 + r) * DIMD + c * 8;
        else                  s = B3p + (size_t)(n0 + r) * DIMD + c * 8;
        srcp[i] = s;
        dsto[i] = (uint32_t)((tile * TILE_H + r * LDT + c * 8) * 2);
    }

    auto load_stage = [&](int s, int kt) {
        uint32_t base = sbase + (uint32_t)(s * STAGE1_H * 2);
#pragma unroll
        for (int i = 0; i < 6; i++) cp16(base + dsto[i], srcp[i] + kt * BK);
        CPCOMMIT();
    };

    const int wm = (wid & 3) * 32, wn = (wid >> 2) * 64;
    const int lrow = lane & 15, lcol = lane >> 4;
    // per-warp ldmatrix base addrs (byte offsets within stage added later)
    uint32_t aA  = sbase + (uint32_t)(((wm + lrow) * LDT + lcol * 8) * 2);
    uint32_t aB1 = sbase + (uint32_t)((TILE_H     + (wn + lrow) * LDT + lcol * 8) * 2);
    uint32_t aB3 = sbase + (uint32_t)((2 * TILE_H + (wn + lrow) * LDT + lcol * 8) * 2);

    float c1[2][8][4], c3[2][8][4];
#pragma unroll
    for (int i = 0; i < 2; i++)
#pragma unroll
        for (int j = 0; j < 8; j++)
#pragma unroll
            for (int u = 0; u < 4; u++) { c1[i][j][u] = 0.f; c3[i][j][u] = 0.f; }

    load_stage(0, 0);
    load_stage(1, 1);

    for (int kt = 0; kt < NK1; kt++) {
        CPWAIT1();
        __syncthreads();
        if (kt + 2 < NK1) load_stage((kt + 2) % 3, kt + 2);
        else CPCOMMIT();
        uint32_t so = (uint32_t)((kt % 3) * STAGE1_H * 2);
#pragma unroll
        for (int ks = 0; ks < 2; ks++) {
            uint32_t ko = so + (uint32_t)(ks * 16 * 2);
            uint32_t a[2][4], br1[4][4], br3[4][4];
#pragma unroll
            for (int i = 0; i < 2; i++) ldsm4(a[i], aA + ko + (uint32_t)(i * 16 * LDT * 2));
#pragma unroll
            for (int p = 0; p < 4; p++) ldsm4(br1[p], aB1 + ko + (uint32_t)(p * 16 * LDT * 2));
#pragma unroll
            for (int p = 0; p < 4; p++) ldsm4(br3[p], aB3 + ko + (uint32_t)(p * 16 * LDT * 2));
#pragma unroll
            for (int i = 0; i < 2; i++)
#pragma unroll
                for (int p = 0; p < 4; p++) {
                    mma16816(c1[i][2 * p],     a[i], br1[p][0], br1[p][2]);
                    mma16816(c1[i][2 * p + 1], a[i], br1[p][1], br1[p][3]);
                    mma16816(c3[i][2 * p],     a[i], br3[p][0], br3[p][2]);
                    mma16816(c3[i][2 * p + 1], a[i], br3[p][1], br3[p][3]);
                }
        }
    }

    // epilogue: silu(h1)*h3 from fragments -> float staging -> coalesced half store
    __syncthreads();
    float* stg = (float*)smem;
    const int qr = lane >> 2, qc = (lane & 3) * 2;
#pragma unroll
    for (int i = 0; i < 2; i++)
#pragma unroll
        for (int j = 0; j < 8; j++) {
            float* op = stg + (wm + i * 16 + qr) * STG_LD + wn + j * 8 + qc;
            float g0 = c1[i][j][0], g1 = c1[i][j][1], g2 = c1[i][j][2], g3 = c1[i][j][3];
            op[0] = (g0 / (1.f + __expf(-g0))) * c3[i][j][0];
            op[1] = (g1 / (1.f + __expf(-g1))) * c3[i][j][1];
            op[8 * STG_LD]     = (g2 / (1.f + __expf(-g2))) * c3[i][j][2];
            op[8 * STG_LD + 1] = (g3 / (1.f + __expf(-g3))) * c3[i][j][3];
        }
    __syncthreads();

    __half* gout = g_acth + (size_t)seg * T_TOK * HID;
    for (int q = tid; q < 128 * 16; q += 256) {
        int row = q >> 4, c = q & 15;
        const float* p = stg + row * STG_LD + c * 8;
        __half2 h[4];
#pragma unroll
        for (int u = 0; u < 4; u++) h[u] = __floats2half2_rn(p[2 * u], p[2 * u + 1]);
        *(uint4*)&gout[(size_t)(m0 + row) * HID + n0 + c * 8] = *(uint4*)h;
    }
}

// ============================================================================
// GEMM2 (mma.sync fp16): part[seg] = act[seg] @ W2^T
// grid = (64, 8, 9); CTA 128x128; warp 32x64
// ============================================================================
__global__ __launch_bounds__(256, 1) void gemm2_kernel()
{
    extern __shared__ char smem[];
    const int tid = threadIdx.x, wid = tid >> 5, lane = tid & 31;

    int seg = blockIdx.z;
    int count; const __half* Bp;
    if (seg == 0) { count = T_TOK; Bp = g_sw2h; }
    else { count = g_counts[seg - 1]; Bp = g_w2h + (size_t)(seg - 1) * DIMD * HID; }
    int m0 = blockIdx.x * BM;
    if (m0 >= count) return;
    int n0 = blockIdx.y * BN;
    const __half* Ap = g_acth + (size_t)seg * T_TOK * HID;

    __half* sH = (__half*)smem;
    uint32_t sbase = (uint32_t)__cvta_generic_to_shared(sH);

    const __half* srcp[4]; uint32_t dsto[4];
#pragma unroll
    for (int i = 0; i < 4; i++) {
        int q = tid + 256 * i;
        int tile = q >> 9;
        int r = (q >> 2) & 127;
        int c = q & 3;
        const __half* s;
        if (tile == 0) s = Ap + (size_t)(m0 + r) * HID + c * 8;
        else           s = Bp + (size_t)(n0 + r) * HID + c * 8;
        srcp[i] = s;
        dsto[i] = (uint32_t)((tile * TILE_H + r * LDT + c * 8) * 2);
    }

    auto load_stage = [&](int s, int kt) {
        uint32_t base = sbase + (uint32_t)(s * STAGE2_H * 2);
#pragma unroll
        for (int i = 0; i < 4; i++) cp16(base + dsto[i], srcp[i] + kt * BK);
        CPCOMMIT();
    };

    const int wm = (wid & 3) * 32, wn = (wid >> 2) * 64;
    const int lrow = lane & 15, lcol = lane >> 4;
    uint32_t aA = sbase + (uint32_t)(((wm + lrow) * LDT + lcol * 8) * 2);
    uint32_t aB = sbase + (uint32_t)((TILE_H + (wn + lrow) * LDT + lcol * 8) * 2);

    float cc[2][8][4];
#pragma unroll
    for (int i = 0; i < 2; i++)
#pragma unroll
        for (int j = 0; j < 8; j++)
#pragma unroll
            for (int u = 0; u < 4; u++) cc[i][j][u] = 0.f;

    load_stage(0, 0);
    load_stage(1, 1);

    for (int kt = 0; kt < NK2; kt++) {
        CPWAIT1();
        __syncthreads();
        if (kt + 2 < NK2) load_stage((kt + 2) % 3, kt + 2);
        else CPCOMMIT();
        uint32_t so = (uint32_t)((kt % 3) * STAGE2_H * 2);
#pragma unroll
        for (int ks = 0; ks < 2; ks++) {
            uint32_t ko = so + (uint32_t)(ks * 16 * 2);
            uint32_t a[2][4], br[4][4];
#pragma unroll
            for (int i = 0; i < 2; i++) ldsm4(a[i], aA + ko + (uint32_t)(i * 16 * LDT * 2));
#pragma unroll
            for (int p = 0; p < 4; p++) ldsm4(br[p], aB + ko + (uint32_t)(p * 16 * LDT * 2));
#pragma unroll
            for (int i = 0; i < 2; i++)
#pragma unroll
                for (int p = 0; p < 4; p++) {
                    mma16816(cc[i][2 * p],     a[i], br[p][0], br[p][2]);
                    mma16816(cc[i][2 * p + 1], a[i], br[p][1], br[p][3]);
                }
        }
    }

    __syncthreads();
    float* stg = (float*)smem;
    const int qr = lane >> 2, qc = (lane & 3) * 2;
#pragma unroll
    for (int i = 0; i < 2; i++)
#pragma unroll
        for (int j = 0; j < 8; j++) {
            float* op = stg + (wm + i * 16 + qr) * STG_LD + wn + j * 8 + qc;
            op[0] = cc[i][j][0];
            op[1] = cc[i][j][1];
            op[8 * STG_LD]     = cc[i][j][2];
            op[8 * STG_LD + 1] = cc[i][j][3];
        }
    __syncthreads();

    float* pout = g_part + (size_t)seg * T_TOK * DIMD;
    for (int q = tid; q < 128 * 32; q += 256) {
        int row = q >> 5, c = q & 31;
        float4 v = *(float4*)&stg[row * STG_LD + c * 4];
        *(float4*)&pout[(size_t)(m0 + row) * DIMD + n0 + c * 4] = v;
    }
}

// ============================================================================
// Combine
// ============================================================================
__global__ __launch_bounds__(256) void combine_kernel(float* __restrict__ y)
{
    int t = blockIdx.x;
    int e0 = g_me[2 * t], e1 = g_me[2 * t + 1];
    int p0 = g_mp[2 * t], p1 = g_mp[2 * t + 1];
    float w0 = g_mw[2 * t], w1 = g_mw[2 * t + 1];
    const float4* s0 = (const float4*)(g_part + (size_t)t * DIMD);
    const float4* pa = (const float4*)(g_part + ((size_t)(1 + e0) * T_TOK + p0) * DIMD);
    const float4* pb = (const float4*)(g_part + ((size_t)(1 + e1) * T_TOK + p1) * DIMD);
    float4* yo = (float4*)(y + (size_t)t * DIMD);
    int i = threadIdx.x;
    float4 a = s0[i], va = pa[i], vb = pb[i];
    yo[i] = make_float4(a.x + w0 * va.x + w1 * vb.x,
                        a.y + w0 * va.y + w1 * vb.y,
                        a.z + w0 * va.z + w1 * vb.z,
                        a.w + w0 * va.w + w1 * vb.w);
}

// ============================================================================
extern "C" void kernel_launch(void* const* d_in, const int* in_sizes, int n_in,
                              void* d_out, int out_size)
{
    const float* x   = (const float*)d_in[0];
    const float* gw  = (const float*)d_in[1];
    const float* w1  = (const float*)d_in[2];
    const float* w2  = (const float*)d_in[3];
    const float* w3  = (const float*)d_in[4];
    const float* sw1 = (const float*)d_in[5];
    const float* sw2 = (const float*)d_in[6];
    const float* sw3 = (const float*)d_in[7];
    float* y = (float*)d_out;

    void* cptr = nullptr;
    cudaGetSymbolAddress(&cptr, g_counts);
    cudaMemsetAsync(cptr, 0, NE * sizeof(int));

    void *xh, *w1h, *w3h, *w2h, *s1h, *s2h, *s3h;
    cudaGetSymbolAddress(&xh,  g_xh);
    cudaGetSymbolAddress(&w1h, g_w1h);
    cudaGetSymbolAddress(&w3h, g_w3h);
    cudaGetSymbolAddress(&w2h, g_w2h);
    cudaGetSymbolAddress(&s1h, g_sw1h);
    cudaGetSymbolAddress(&s2h, g_sw2h);
    cudaGetSymbolAddress(&s3h, g_sw3h);

    const int nx  = T_TOK * DIMD / 4;
    const int nw  = NE * HID * DIMD / 4;
    const int nsw = HID * DIMD / 4;
    tohalf_kernel<<<(nx  + 255) / 256, 256>>>(x,   (__half*)xh,  nx);
    tohalf_kernel<<<(nw  + 255) / 256, 256>>>(w1,  (__half*)w1h, nw);
    tohalf_kernel<<<(nw  + 255) / 256, 256>>>(w3,  (__half*)w3h, nw);
    tohalf_kernel<<<(nw  + 255) / 256, 256>>>(w2,  (__half*)w2h, nw);
    tohalf_kernel<<<(nsw + 255) / 256, 256>>>(sw1, (__half*)s1h, nsw);
    tohalf_kernel<<<(nsw + 255) / 256, 256>>>(sw2, (__half*)s2h, nsw);
    tohalf_kernel<<<(nsw + 255) / 256, 256>>>(sw3, (__half*)s3h, nsw);

    gate_kernel<<<T_TOK / 8, 256>>>(x, gw);

    cudaFuncSetAttribute(gemm1_kernel, cudaFuncAttributeMaxDynamicSharedMemorySize, SMEM1);
    cudaFuncSetAttribute(gemm2_kernel, cudaFuncAttributeMaxDynamicSharedMemorySize, SMEM2);

    gemm1_kernel<<<dim3(T_TOK / BM, HID / BN, NE + 1), 256, SMEM1>>>();
    gemm2_kernel<<<dim3(T_TOK / BM, DIMD / BN, NE + 1), 256, SMEM2>>>();
    combine_kernel<<<T_TOK, 256>>>(y);
}

// round 13
// speedup vs baseline: 1.4156x; 1.4156x over previous
#include <cuda_runtime.h>
#include <cuda_fp16.h>
#include <mma.h>
#include <cstdint>

using namespace nvcuda;

#define T_TOK 8192
#define DIMD  1024
#define HID   2816
#define NE    8

#define BM 128
#define BN 128
#define BK 32
#define NT 512            // threads per GEMM CTA (16 warps, 4x4 grid, warp tile 32x32)
#define LDT 40            // halves per smem row (80B pitch, 16B aligned)
#define STG_LD 132        // floats per staging row

#define TILE_H   (BM * LDT)            // 5120 halves per tile
#define STAGE1_H (3 * TILE_H)
#define STAGE2_H (2 * TILE_H)
#define SMEM1 (3 * STAGE1_H * 2)       // 92160 B
#define SMEM2 (128 * STG_LD * 4)       // 67584 B (>= pipeline 61440)

#define NK1 (DIMD / BK)   // 32
#define NK2 (HID / BK)    // 88

// ---------------- static scratch (allocation-free) ----------------
__device__ int    g_counts[NE];
__device__ int    g_list[NE * T_TOK];
__device__ int    g_me[2 * T_TOK];
__device__ int    g_mp[2 * T_TOK];
__device__ float  g_mw[2 * T_TOK];
__device__ __half g_xh  [(size_t)T_TOK * DIMD];
__device__ __half g_w1h [(size_t)NE * HID * DIMD];
__device__ __half g_w3h [(size_t)NE * HID * DIMD];
__device__ __half g_w2h [(size_t)NE * DIMD * HID];
__device__ __half g_sw1h[(size_t)HID * DIMD];
__device__ __half g_sw3h[(size_t)HID * DIMD];
__device__ __half g_sw2h[(size_t)DIMD * HID];
__device__ __half g_acth[(size_t)(NE + 1) * T_TOK * HID];
__device__ float  g_part[(size_t)(NE + 1) * T_TOK * DIMD];

// ---------------- helpers ----------------
__device__ __forceinline__ void cp16(uint32_t d, const void* s) {
    asm volatile("cp.async.ca.shared.global [%0], [%1], 16;\n" :: "r"(d), "l"(s));
}
#define CPCOMMIT() asm volatile("cp.async.commit_group;\n" ::: "memory")
#define CPWAIT1()  asm volatile("cp.async.wait_group 1;\n" ::: "memory")

// ============================================================================
// f32 -> f16 conversion pre-pass
// ============================================================================
__global__ __launch_bounds__(256) void tohalf_kernel(const float* __restrict__ src,
                                                     __half* __restrict__ dst, int n4)
{
    int i = blockIdx.x * 256 + threadIdx.x;
    if (i < n4) {
        float4 v = ((const float4*)src)[i];
        __half2 a = __floats2half2_rn(v.x, v.y);
        __half2 b = __floats2half2_rn(v.z, v.w);
        ((__half2*)dst)[2 * i]     = a;
        ((__half2*)dst)[2 * i + 1] = b;
    }
}

// ============================================================================
// Gate
// ============================================================================
__global__ __launch_bounds__(256) void gate_kernel(const float* __restrict__ x,
                                                   const float* __restrict__ gw)
{
    __shared__ float sgw[NE * DIMD];
    for (int i = threadIdx.x; i < NE * DIMD; i += 256) sgw[i] = gw[i];
    __syncthreads();

    int warp = threadIdx.x >> 5, lane = threadIdx.x & 31;
    int t = blockIdx.x * 8 + warp;
    const float* xp = x + (size_t)t * DIMD;

    float acc[NE];
#pragma unroll
    for (int e = 0; e < NE; e++) acc[e] = 0.f;
    for (int k = lane; k < DIMD; k += 32) {
        float xv = xp[k];
#pragma unroll
        for (int e = 0; e < NE; e++) acc[e] += xv * sgw[e * DIMD + k];
    }
#pragma unroll
    for (int e = 0; e < NE; e++)
#pragma unroll
        for (int o = 16; o > 0; o >>= 1) acc[e] += __shfl_xor_sync(0xffffffffu, acc[e], o);

    if (lane == 0) {
        int e0 = 0; float l0 = acc[0];
#pragma unroll
        for (int e = 1; e < NE; e++) if (acc[e] > l0) { l0 = acc[e]; e0 = e; }
        int e1 = (e0 == 0) ? 1 : 0; float l1 = acc[e1];
#pragma unroll
        for (int e = 0; e < NE; e++) if (e != e0 && acc[e] > l1) { l1 = acc[e]; e1 = e; }
        float w0 = 1.f / (1.f + __expf(l1 - l0));
        float w1 = 1.f - w0;
        int p0 = atomicAdd(&g_counts[e0], 1);
        g_list[e0 * T_TOK + p0] = t;
        int p1 = atomicAdd(&g_counts[e1], 1);
        g_list[e1 * T_TOK + p1] = t;
        g_me[2 * t] = e0; g_me[2 * t + 1] = e1;
        g_mp[2 * t] = p0; g_mp[2 * t + 1] = p1;
        g_mw[2 * t] = w0; g_mw[2 * t + 1] = w1;
    }
}

// ============================================================================
// GEMM1 (fp16 wmma, 512 thr, warp 32x32): act = silu(X W1^T) * (X W3^T)
// grid = (64, 22, 9)
// ============================================================================
__global__ __launch_bounds__(NT, 1) void gemm1_kernel()
{
    extern __shared__ char smem[];
    const int tid = threadIdx.x, wid = tid >> 5;

    int seg = blockIdx.z;
    int count; const int* list; const __half* B1p; const __half* B3p;
    if (seg == 0) { count = T_TOK; list = nullptr; B1p = g_sw1h; B3p = g_sw3h; }
    else {
        int e = seg - 1;
        count = g_counts[e];
        list  = g_list + e * T_TOK;
        B1p = g_w1h + (size_t)e * HID * DIMD;
        B3p = g_w3h + (size_t)e * HID * DIMD;
    }
    int m0 = blockIdx.x * BM;
    if (m0 >= count) return;
    int n0 = blockIdx.y * BN;

    __half* sH = (__half*)smem;
    uint32_t sbase = (uint32_t)__cvta_generic_to_shared(sH);

    // cp.async map: 1536 16B-chunks / stage, 3 per thread
    const __half* srcp[3]; uint32_t dsto[3];
#pragma unroll
    for (int i = 0; i < 3; i++) {
        int q = tid + NT * i;
        int tile = q >> 9;            // 0=A, 1=B1, 2=B3
        int r = (q >> 2) & 127;
        int c = q & 3;
        const __half* s;
        if (tile == 0) {
            int gr = m0 + r;
            int tok = (gr < count) ? (list ? list[gr] : gr) : 0;
            s = g_xh + (size_t)tok * DIMD + c * 8;
        } else if (tile == 1) s = B1p + (size_t)(n0 + r) * DIMD + c * 8;
        else                  s = B3p + (size_t)(n0 + r) * DIMD + c * 8;
        srcp[i] = s;
        dsto[i] = (uint32_t)((tile * TILE_H + r * LDT + c * 8) * 2);
    }

    auto load_stage = [&](int s, int kt) {
        uint32_t base = sbase + (uint32_t)(s * STAGE1_H * 2);
#pragma unroll
        for (int i = 0; i < 3; i++) cp16(base + dsto[i], srcp[i] + kt * BK);
        CPCOMMIT();
    };

    wmma::fragment<wmma::accumulator, 16, 16, 16, float> fc1[2][2], fc3[2][2];
#pragma unroll
    for (int i = 0; i < 2; i++)
#pragma unroll
        for (int j = 0; j < 2; j++) { wmma::fill_fragment(fc1[i][j], 0.f); wmma::fill_fragment(fc3[i][j], 0.f); }

    const int wm = (wid & 3) * 32, wn = (wid >> 2) * 32;

    load_stage(0, 0);
    load_stage(1, 1);

    for (int kt = 0; kt < NK1; kt++) {
        CPWAIT1();
        __syncthreads();
        if (kt + 2 < NK1) load_stage((kt + 2) % 3, kt + 2);
        else CPCOMMIT();   // keep group FIFO arithmetic uniform
        int s = kt % 3;
        const __half* A  = sH + s * STAGE1_H;
        const __half* B1 = A + TILE_H;
        const __half* B3 = A + 2 * TILE_H;
#pragma unroll
        for (int kk = 0; kk < BK; kk += 16) {
            wmma::fragment<wmma::matrix_a, 16, 16, 16, __half, wmma::row_major> fa[2];
#pragma unroll
            for (int i = 0; i < 2; i++)
                wmma::load_matrix_sync(fa[i], A + (wm + i * 16) * LDT + kk, LDT);
#pragma unroll
            for (int j = 0; j < 2; j++) {
                wmma::fragment<wmma::matrix_b, 16, 16, 16, __half, wmma::col_major> fb;
                wmma::load_matrix_sync(fb, B1 + (wn + j * 16) * LDT + kk, LDT);
#pragma unroll
                for (int i = 0; i < 2; i++) wmma::mma_sync(fc1[i][j], fa[i], fb, fc1[i][j]);
                wmma::load_matrix_sync(fb, B3 + (wn + j * 16) * LDT + kk, LDT);
#pragma unroll
                for (int i = 0; i < 2; i++) wmma::mma_sync(fc3[i][j], fa[i], fb, fc3[i][j]);
            }
        }
    }

    // epilogue: silu(h1)*h3 -> float staging -> coalesced half store
    __syncthreads();
    float* stg = (float*)smem;
#pragma unroll
    for (int i = 0; i < 2; i++)
#pragma unroll
        for (int j = 0; j < 2; j++) {
#pragma unroll
            for (int el = 0; el < fc1[i][j].num_elements; el++) {
                float h1 = fc1[i][j].x[el];
                fc1[i][j].x[el] = (h1 / (1.f + __expf(-h1))) * fc3[i][j].x[el];
            }
            wmma::store_matrix_sync(stg + (wm + i * 16) * STG_LD + wn + j * 16,
                                    fc1[i][j], STG_LD, wmma::mem_row_major);
        }
    __syncthreads();

    __half* gout = g_acth + (size_t)seg * T_TOK * HID;
    for (int q = tid; q < 128 * 16; q += NT) {   // 16B chunks of 8 halves
        int row = q >> 4, c = q & 15;
        const float* p = stg + row * STG_LD + c * 8;
        __half2 h[4];
#pragma unroll
        for (int u = 0; u < 4; u++) h[u] = __floats2half2_rn(p[2 * u], p[2 * u + 1]);
        *(uint4*)&gout[(size_t)(m0 + row) * HID + n0 + c * 8] = *(uint4*)h;
    }
}

// ============================================================================
// GEMM2 (fp16 wmma, 512 thr, warp 32x32): part[seg] = act[seg] @ W2^T
// grid = (64, 8, 9)
// ============================================================================
__global__ __launch_bounds__(NT, 1) void gemm2_kernel()
{
    extern __shared__ char smem[];
    const int tid = threadIdx.x, wid = tid >> 5;

    int seg = blockIdx.z;
    int count; const __half* Bp;
    if (seg == 0) { count = T_TOK; Bp = g_sw2h; }
    else { count = g_counts[seg - 1]; Bp = g_w2h + (size_t)(seg - 1) * DIMD * HID; }
    int m0 = blockIdx.x * BM;
    if (m0 >= count) return;
    int n0 = blockIdx.y * BN;
    const __half* Ap = g_acth + (size_t)seg * T_TOK * HID;

    __half* sH = (__half*)smem;
    uint32_t sbase = (uint32_t)__cvta_generic_to_shared(sH);

    const __half* srcp[2]; uint32_t dsto[2];
#pragma unroll
    for (int i = 0; i < 2; i++) {
        int q = tid + NT * i;
        int tile = q >> 9;            // 0=A, 1=B
        int r = (q >> 2) & 127;
        int c = q & 3;
        const __half* s;
        if (tile == 0) s = Ap + (size_t)(m0 + r) * HID + c * 8;   // padded segment: in-bounds
        else           s = Bp + (size_t)(n0 + r) * HID + c * 8;
        srcp[i] = s;
        dsto[i] = (uint32_t)((tile * TILE_H + r * LDT + c * 8) * 2);
    }

    auto load_stage = [&](int s, int kt) {
        uint32_t base = sbase + (uint32_t)(s * STAGE2_H * 2);
#pragma unroll
        for (int i = 0; i < 2; i++) cp16(base + dsto[i], srcp[i] + kt * BK);
        CPCOMMIT();
    };

    wmma::fragment<wmma::accumulator, 16, 16, 16, float> fc[2][2];
#pragma unroll
    for (int i = 0; i < 2; i++)
#pragma unroll
        for (int j = 0; j < 2; j++) wmma::fill_fragment(fc[i][j], 0.f);

    const int wm = (wid & 3) * 32, wn = (wid >> 2) * 32;

    load_stage(0, 0);
    load_stage(1, 1);

    for (int kt = 0; kt < NK2; kt++) {
        CPWAIT1();
        __syncthreads();
        if (kt + 2 < NK2) load_stage((kt + 2) % 3, kt + 2);
        else CPCOMMIT();
        int s = kt % 3;
        const __half* A = sH + s * STAGE2_H;
        const __half* B = A + TILE_H;
#pragma unroll
        for (int kk = 0; kk < BK; kk += 16) {
            wmma::fragment<wmma::matrix_a, 16, 16, 16, __half, wmma::row_major> fa[2];
#pragma unroll
            for (int i = 0; i < 2; i++)
                wmma::load_matrix_sync(fa[i], A + (wm + i * 16) * LDT + kk, LDT);
#pragma unroll
            for (int j = 0; j < 2; j++) {
                wmma::fragment<wmma::matrix_b, 16, 16, 16, __half, wmma::col_major> fb;
                wmma::load_matrix_sync(fb, B + (wn + j * 16) * LDT + kk, LDT);
#pragma unroll
                for (int i = 0; i < 2; i++) wmma::mma_sync(fc[i][j], fa[i], fb, fc[i][j]);
            }
        }
    }

    __syncthreads();
    float* stg = (float*)smem;
#pragma unroll
    for (int i = 0; i < 2; i++)
#pragma unroll
        for (int j = 0; j < 2; j++)
            wmma::store_matrix_sync(stg + (wm + i * 16) * STG_LD + wn + j * 16,
                                    fc[i][j], STG_LD, wmma::mem_row_major);
    __syncthreads();

    float* pout = g_part + (size_t)seg * T_TOK * DIMD;
    for (int q = tid; q < 128 * 32; q += NT) {   // float4 chunks
        int row = q >> 5, c = q & 31;
        float4 v = *(float4*)&stg[row * STG_LD + c * 4];
        *(float4*)&pout[(size_t)(m0 + row) * DIMD + n0 + c * 4] = v;
    }
}

// ============================================================================
// Combine
// ============================================================================
__global__ __launch_bounds__(256) void combine_kernel(float* __restrict__ y)
{
    int t = blockIdx.x;
    int e0 = g_me[2 * t], e1 = g_me[2 * t + 1];
    int p0 = g_mp[2 * t], p1 = g_mp[2 * t + 1];
    float w0 = g_mw[2 * t], w1 = g_mw[2 * t + 1];
    const float4* s0 = (const float4*)(g_part + (size_t)t * DIMD);
    const float4* pa = (const float4*)(g_part + ((size_t)(1 + e0) * T_TOK + p0) * DIMD);
    const float4* pb = (const float4*)(g_part + ((size_t)(1 + e1) * T_TOK + p1) * DIMD);
    float4* yo = (float4*)(y + (size_t)t * DIMD);
    int i = threadIdx.x;
    float4 a = s0[i], va = pa[i], vb = pb[i];
    yo[i] = make_float4(a.x + w0 * va.x + w1 * vb.x,
                        a.y + w0 * va.y + w1 * vb.y,
                        a.z + w0 * va.z + w1 * vb.z,
                        a.w + w0 * va.w + w1 * vb.w);
}

// ============================================================================
extern "C" void kernel_launch(void* const* d_in, const int* in_sizes, int n_in,
                              void* d_out, int out_size)
{
    const float* x   = (const float*)d_in[0];
    const float* gw  = (const float*)d_in[1];
    const float* w1  = (const float*)d_in[2];
    const float* w2  = (const float*)d_in[3];
    const float* w3  = (const float*)d_in[4];
    const float* sw1 = (const float*)d_in[5];
    const float* sw2 = (const float*)d_in[6];
    const float* sw3 = (const float*)d_in[7];
    float* y = (float*)d_out;

    void* cptr = nullptr;
    cudaGetSymbolAddress(&cptr, g_counts);
    cudaMemsetAsync(cptr, 0, NE * sizeof(int));

    void *xh, *w1h, *w3h, *w2h, *s1h, *s2h, *s3h;
    cudaGetSymbolAddress(&xh,  g_xh);
    cudaGetSymbolAddress(&w1h, g_w1h);
    cudaGetSymbolAddress(&w3h, g_w3h);
    cudaGetSymbolAddress(&w2h, g_w2h);
    cudaGetSymbolAddress(&s1h, g_sw1h);
    cudaGetSymbolAddress(&s2h, g_sw2h);
    cudaGetSymbolAddress(&s3h, g_sw3h);

    const int nx  = T_TOK * DIMD / 4;
    const int nw  = NE * HID * DIMD / 4;
    const int nsw = HID * DIMD / 4;
    tohalf_kernel<<<(nx  + 255) / 256, 256>>>(x,   (__half*)xh,  nx);
    tohalf_kernel<<<(nw  + 255) / 256, 256>>>(w1,  (__half*)w1h, nw);
    tohalf_kernel<<<(nw  + 255) / 256, 256>>>(w3,  (__half*)w3h, nw);
    tohalf_kernel<<<(nw  + 255) / 256, 256>>>(w2,  (__half*)w2h, nw);
    tohalf_kernel<<<(nsw + 255) / 256, 256>>>(sw1, (__half*)s1h, nsw);
    tohalf_kernel<<<(nsw + 255) / 256, 256>>>(sw2, (__half*)s2h, nsw);
    tohalf_kernel<<<(nsw + 255) / 256, 256>>>(sw3, (__half*)s3h, nsw);

    gate_kernel<<<T_TOK / 8, 256>>>(x, gw);

    cudaFuncSetAttribute(gemm1_kernel, cudaFuncAttributeMaxDynamicSharedMemorySize, SMEM1);
    cudaFuncSetAttribute(gemm2_kernel, cudaFuncAttributeMaxDynamicSharedMemorySize, SMEM2);

    gemm1_kernel<<<dim3(T_TOK / BM, HID / BN, NE + 1), NT, SMEM1>>>();
    gemm2_kernel<<<dim3(T_TOK / BM, DIMD / BN, NE + 1), NT, SMEM2>>>();
    combine_kernel<<<T_TOK, 256>>>(y);
}

// round 16
// speedup vs baseline: 1.6985x; 1.1999x over previous
#include <cuda_runtime.h>
#include <cuda_fp16.h>
#include <mma.h>
#include <cstdint>

using namespace nvcuda;

#define T_TOK 8192
#define DIMD  1024
#define HID   2816
#define NE    8

#define BM 128
#define BN 128
#define BK 64
#define NT 512            // 16 warps, 4x4 grid, warp tile 32x32
#define LDT 72            // halves per smem row (144B pitch; rows hit distinct 16B banks)
#define STG_LD 132        // floats per staging row

#define TILE_H   (BM * LDT)            // 9216 halves (18432 B)
#define STAGE1_H (3 * TILE_H)          // A, B1, B3
#define STAGE2_H (2 * TILE_H)          // A, B
#define SMEM1 (3 * STAGE1_H * 2)       // 165888 B
#define SMEM2 (3 * STAGE2_H * 2)       // 110592 B (>= staging 67584)

#define NK1 (DIMD / BK)   // 16
#define NK2 (HID / BK)    // 44

// ---------------- static scratch (allocation-free) ----------------
__device__ int    g_counts[NE];
__device__ int    g_list[NE * T_TOK];
__device__ int    g_me[2 * T_TOK];
__device__ int    g_mp[2 * T_TOK];
__device__ float  g_mw[2 * T_TOK];
__device__ __half g_xh  [(size_t)T_TOK * DIMD];
__device__ __half g_w1h [(size_t)NE * HID * DIMD];
__device__ __half g_w3h [(size_t)NE * HID * DIMD];
__device__ __half g_w2h [(size_t)NE * DIMD * HID];
__device__ __half g_sw1h[(size_t)HID * DIMD];
__device__ __half g_sw3h[(size_t)HID * DIMD];
__device__ __half g_sw2h[(size_t)DIMD * HID];
__device__ __half g_acth[(size_t)(NE + 1) * T_TOK * HID];
__device__ float  g_part[(size_t)(NE + 1) * T_TOK * DIMD];

// ---------------- helpers ----------------
__device__ __forceinline__ void cp16(uint32_t d, const void* s) {
    asm volatile("cp.async.ca.shared.global [%0], [%1], 16;\n" :: "r"(d), "l"(s));
}
#define CPCOMMIT() asm volatile("cp.async.commit_group;\n" ::: "memory")
#define CPWAIT1()  asm volatile("cp.async.wait_group 1;\n" ::: "memory")

// ============================================================================
// f32 -> f16 conversion pre-pass
// ============================================================================
__global__ __launch_bounds__(256) void tohalf_kernel(const float* __restrict__ src,
                                                     __half* __restrict__ dst, int n4)
{
    int i = blockIdx.x * 256 + threadIdx.x;
    if (i < n4) {
        float4 v = ((const float4*)src)[i];
        __half2 a = __floats2half2_rn(v.x, v.y);
        __half2 b = __floats2half2_rn(v.z, v.w);
        ((__half2*)dst)[2 * i]     = a;
        ((__half2*)dst)[2 * i + 1] = b;
    }
}

// ============================================================================
// Gate
// ============================================================================
__global__ __launch_bounds__(256) void gate_kernel(const float* __restrict__ x,
                                                   const float* __restrict__ gw)
{
    __shared__ float sgw[NE * DIMD];
    for (int i = threadIdx.x; i < NE * DIMD; i += 256) sgw[i] = gw[i];
    __syncthreads();

    int warp = threadIdx.x >> 5, lane = threadIdx.x & 31;
    int t = blockIdx.x * 8 + warp;
    const float* xp = x + (size_t)t * DIMD;

    float acc[NE];
#pragma unroll
    for (int e = 0; e < NE; e++) acc[e] = 0.f;
    for (int k = lane; k < DIMD; k += 32) {
        float xv = xp[k];
#pragma unroll
        for (int e = 0; e < NE; e++) acc[e] += xv * sgw[e * DIMD + k];
    }
#pragma unroll
    for (int e = 0; e < NE; e++)
#pragma unroll
        for (int o = 16; o > 0; o >>= 1) acc[e] += __shfl_xor_sync(0xffffffffu, acc[e], o);

    if (lane == 0) {
        int e0 = 0; float l0 = acc[0];
#pragma unroll
        for (int e = 1; e < NE; e++) if (acc[e] > l0) { l0 = acc[e]; e0 = e; }
        int e1 = (e0 == 0) ? 1 : 0; float l1 = acc[e1];
#pragma unroll
        for (int e = 0; e < NE; e++) if (e != e0 && acc[e] > l1) { l1 = acc[e]; e1 = e; }
        float w0 = 1.f / (1.f + __expf(l1 - l0));
        float w1 = 1.f - w0;
        int p0 = atomicAdd(&g_counts[e0], 1);
        g_list[e0 * T_TOK + p0] = t;
        int p1 = atomicAdd(&g_counts[e1], 1);
        g_list[e1 * T_TOK + p1] = t;
        g_me[2 * t] = e0; g_me[2 * t + 1] = e1;
        g_mp[2 * t] = p0; g_mp[2 * t + 1] = p1;
        g_mw[2 * t] = w0; g_mw[2 * t + 1] = w1;
    }
}

// ============================================================================
// GEMM1 (fp16 wmma, BK=64): act = silu(X W1^T) * (X W3^T)
// grid = (64, 22, 9)
// ============================================================================
__global__ __launch_bounds__(NT, 1) void gemm1_kernel()
{
    extern __shared__ char smem[];
    const int tid = threadIdx.x, wid = tid >> 5;

    int seg = blockIdx.z;
    int count; const int* list; const __half* B1p; const __half* B3p;
    if (seg == 0) { count = T_TOK; list = nullptr; B1p = g_sw1h; B3p = g_sw3h; }
    else {
        int e = seg - 1;
        count = g_counts[e];
        list  = g_list + e * T_TOK;
        B1p = g_w1h + (size_t)e * HID * DIMD;
        B3p = g_w3h + (size_t)e * HID * DIMD;
    }
    int m0 = blockIdx.x * BM;
    if (m0 >= count) return;
    int n0 = blockIdx.y * BN;

    __half* sH = (__half*)smem;
    uint32_t sbase = (uint32_t)__cvta_generic_to_shared(sH);

    // cp.async map: 3 tiles x 128 rows x 8 data-chunks (64 halves) = 3072 / 512 = 6 per thread
    const __half* srcp[6]; uint32_t dsto[6];
#pragma unroll
    for (int i = 0; i < 6; i++) {
        int q = tid + NT * i;
        int tile = q >> 10;           // 0=A, 1=B1, 2=B3   (1024 chunks per tile)
        int r = (q >> 3) & 127;
        int c = q & 7;                // 16B chunk in the 64-half data region
        const __half* s;
        if (tile == 0) {
            int gr = m0 + r;
            int tok = (gr < count) ? (list ? list[gr] : gr) : 0;
            s = g_xh + (size_t)tok * DIMD + c * 8;
        } else if (tile == 1) s = B1p + (size_t)(n0 + r) * DIMD + c * 8;
        else                  s = B3p + (size_t)(n0 + r) * DIMD + c * 8;
        srcp[i] = s;
        dsto[i] = (uint32_t)((tile * TILE_H + r * LDT + c * 8) * 2);
    }

    auto load_stage = [&](int s, int kt) {
        uint32_t base = sbase + (uint32_t)(s * STAGE1_H * 2);
#pragma unroll
        for (int i = 0; i < 6; i++) cp16(base + dsto[i], srcp[i] + kt * BK);
        CPCOMMIT();
    };

    wmma::fragment<wmma::accumulator, 16, 16, 16, float> fc1[2][2], fc3[2][2];
#pragma unroll
    for (int i = 0; i < 2; i++)
#pragma unroll
        for (int j = 0; j < 2; j++) { wmma::fill_fragment(fc1[i][j], 0.f); wmma::fill_fragment(fc3[i][j], 0.f); }

    const int wm = (wid & 3) * 32, wn = (wid >> 2) * 32;

    load_stage(0, 0);
    load_stage(1, 1);

    for (int kt = 0; kt < NK1; kt++) {
        CPWAIT1();
        __syncthreads();
        if (kt + 2 < NK1) load_stage((kt + 2) % 3, kt + 2);
        else CPCOMMIT();   // keep group FIFO arithmetic uniform
        int s = kt % 3;
        const __half* A  = sH + s * STAGE1_H;
        const __half* B1 = A + TILE_H;
        const __half* B3 = A + 2 * TILE_H;
#pragma unroll
        for (int kk = 0; kk < BK; kk += 16) {
            wmma::fragment<wmma::matrix_a, 16, 16, 16, __half, wmma::row_major> fa[2];
#pragma unroll
            for (int i = 0; i < 2; i++)
                wmma::load_matrix_sync(fa[i], A + (wm + i * 16) * LDT + kk, LDT);
#pragma unroll
            for (int j = 0; j < 2; j++) {
                wmma::fragment<wmma::matrix_b, 16, 16, 16, __half, wmma::col_major> fb;
                wmma::load_matrix_sync(fb, B1 + (wn + j * 16) * LDT + kk, LDT);
#pragma unroll
                for (int i = 0; i < 2; i++) wmma::mma_sync(fc1[i][j], fa[i], fb, fc1[i][j]);
                wmma::load_matrix_sync(fb, B3 + (wn + j * 16) * LDT + kk, LDT);
#pragma unroll
                for (int i = 0; i < 2; i++) wmma::mma_sync(fc3[i][j], fa[i], fb, fc3[i][j]);
            }
        }
    }

    // epilogue: silu(h1)*h3 -> float staging -> coalesced half store
    __syncthreads();
    float* stg = (float*)smem;
#pragma unroll
    for (int i = 0; i < 2; i++)
#pragma unroll
        for (int j = 0; j < 2; j++) {
#pragma unroll
            for (int el = 0; el < fc1[i][j].num_elements; el++) {
                float h1 = fc1[i][j].x[el];
                fc1[i][j].x[el] = (h1 / (1.f + __expf(-h1))) * fc3[i][j].x[el];
            }
            wmma::store_matrix_sync(stg + (wm + i * 16) * STG_LD + wn + j * 16,
                                    fc1[i][j], STG_LD, wmma::mem_row_major);
        }
    __syncthreads();

    __half* gout = g_acth + (size_t)seg * T_TOK * HID;
    for (int q = tid; q < 128 * 16; q += NT) {   // 16B chunks of 8 halves
        int row = q >> 4, c = q & 15;
        const float* p = stg + row * STG_LD + c * 8;
        __half2 h[4];
#pragma unroll
        for (int u = 0; u < 4; u++) h[u] = __floats2half2_rn(p[2 * u], p[2 * u + 1]);
        *(uint4*)&gout[(size_t)(m0 + row) * HID + n0 + c * 8] = *(uint4*)h;
    }
}

// ============================================================================
// GEMM2 (fp16 wmma, BK=64): part[seg] = act[seg] @ W2^T
// grid = (64, 8, 9)
// ============================================================================
__global__ __launch_bounds__(NT, 1) void gemm2_kernel()
{
    extern __shared__ char smem[];
    const int tid = threadIdx.x, wid = tid >> 5;

    int seg = blockIdx.z;
    int count; const __half* Bp;
    if (seg == 0) { count = T_TOK; Bp = g_sw2h; }
    else { count = g_counts[seg - 1]; Bp = g_w2h + (size_t)(seg - 1) * DIMD * HID; }
    int m0 = blockIdx.x * BM;
    if (m0 >= count) return;
    int n0 = blockIdx.y * BN;
    const __half* Ap = g_acth + (size_t)seg * T_TOK * HID;

    __half* sH = (__half*)smem;
    uint32_t sbase = (uint32_t)__cvta_generic_to_shared(sH);

    // 2 tiles x 1024 chunks = 2048 / 512 = 4 per thread
    const __half* srcp[4]; uint32_t dsto[4];
#pragma unroll
    for (int i = 0; i < 4; i++) {
        int q = tid + NT * i;
        int tile = q >> 10;           // 0=A, 1=B
        int r = (q >> 3) & 127;
        int c = q & 7;
        const __half* s;
        if (tile == 0) s = Ap + (size_t)(m0 + r) * HID + c * 8;   // padded segment: in-bounds
        else           s = Bp + (size_t)(n0 + r) * HID + c * 8;
        srcp[i] = s;
        dsto[i] = (uint32_t)((tile * TILE_H + r * LDT + c * 8) * 2);
    }

    auto load_stage = [&](int s, int kt) {
        uint32_t base = sbase + (uint32_t)(s * STAGE2_H * 2);
#pragma unroll
        for (int i = 0; i < 4; i++) cp16(base + dsto[i], srcp[i] + kt * BK);
        CPCOMMIT();
    };

    wmma::fragment<wmma::accumulator, 16, 16, 16, float> fc[2][2];
#pragma unroll
    for (int i = 0; i < 2; i++)
#pragma unroll
        for (int j = 0; j < 2; j++) wmma::fill_fragment(fc[i][j], 0.f);

    const int wm = (wid & 3) * 32, wn = (wid >> 2) * 32;

    load_stage(0, 0);
    load_stage(1, 1);

    for (int kt = 0; kt < NK2; kt++) {
        CPWAIT1();
        __syncthreads();
        if (kt + 2 < NK2) load_stage((kt + 2) % 3, kt + 2);
        else CPCOMMIT();
        int s = kt % 3;
        const __half* A = sH + s * STAGE2_H;
        const __half* B = A + TILE_H;
#pragma unroll
        for (int kk = 0; kk < BK; kk += 16) {
            wmma::fragment<wmma::matrix_a, 16, 16, 16, __half, wmma::row_major> fa[2];
#pragma unroll
            for (int i = 0; i < 2; i++)
                wmma::load_matrix_sync(fa[i], A + (wm + i * 16) * LDT + kk, LDT);
#pragma unroll
            for (int j = 0; j < 2; j++) {
                wmma::fragment<wmma::matrix_b, 16, 16, 16, __half, wmma::col_major> fb;
                wmma::load_matrix_sync(fb, B + (wn + j * 16) * LDT + kk, LDT);
#pragma unroll
                for (int i = 0; i < 2; i++) wmma::mma_sync(fc[i][j], fa[i], fb, fc[i][j]);
            }
        }
    }

    __syncthreads();
    float* stg = (float*)smem;
#pragma unroll
    for (int i = 0; i < 2; i++)
#pragma unroll
        for (int j = 0; j < 2; j++)
            wmma::store_matrix_sync(stg + (wm + i * 16) * STG_LD + wn + j * 16,
                                    fc[i][j], STG_LD, wmma::mem_row_major);
    __syncthreads();

    float* pout = g_part + (size_t)seg * T_TOK * DIMD;
    for (int q = tid; q < 128 * 32; q += NT) {   // float4 chunks
        int row = q >> 5, c = q & 31;
        float4 v = *(float4*)&stg[row * STG_LD + c * 4];
        *(float4*)&pout[(size_t)(m0 + row) * DIMD + n0 + c * 4] = v;
    }
}

// ============================================================================
// Combine
// ============================================================================
__global__ __launch_bounds__(256) void combine_kernel(float* __restrict__ y)
{
    int t = blockIdx.x;
    int e0 = g_me[2 * t], e1 = g_me[2 * t + 1];
    int p0 = g_mp[2 * t], p1 = g_mp[2 * t + 1];
    float w0 = g_mw[2 * t], w1 = g_mw[2 * t + 1];
    const float4* s0 = (const float4*)(g_part + (size_t)t * DIMD);
    const float4* pa = (const float4*)(g_part + ((size_t)(1 + e0) * T_TOK + p0) * DIMD);
    const float4* pb = (const float4*)(g_part + ((size_t)(1 + e1) * T_TOK + p1) * DIMD);
    float4* yo = (float4*)(y + (size_t)t * DIMD);
    int i = threadIdx.x;
    float4 a = s0[i], va = pa[i], vb = pb[i];
    yo[i] = make_float4(a.x + w0 * va.x + w1 * vb.x,
                        a.y + w0 * va.y + w1 * vb.y,
                        a.z + w0 * va.z + w1 * vb.z,
                        a.w + w0 * va.w + w1 * vb.w);
}

// ============================================================================
extern "C" void kernel_launch(void* const* d_in, const int* in_sizes, int n_in,
                              void* d_out, int out_size)
{
    const float* x   = (const float*)d_in[0];
    const float* gw  = (const float*)d_in[1];
    const float* w1  = (const float*)d_in[2];
    const float* w2  = (const float*)d_in[3];
    const float* w3  = (const float*)d_in[4];
    const float* sw1 = (const float*)d_in[5];
    const float* sw2 = (const float*)d_in[6];
    const float* sw3 = (const float*)d_in[7];
    float* y = (float*)d_out;

    void* cptr = nullptr;
    cudaGetSymbolAddress(&cptr, g_counts);
    cudaMemsetAsync(cptr, 0, NE * sizeof(int));

    void *xh, *w1h, *w3h, *w2h, *s1h, *s2h, *s3h;
    cudaGetSymbolAddress(&xh,  g_xh);
    cudaGetSymbolAddress(&w1h, g_w1h);
    cudaGetSymbolAddress(&w3h, g_w3h);
    cudaGetSymbolAddress(&w2h, g_w2h);
    cudaGetSymbolAddress(&s1h, g_sw1h);
    cudaGetSymbolAddress(&s2h, g_sw2h);
    cudaGetSymbolAddress(&s3h, g_sw3h);

    const int nx  = T_TOK * DIMD / 4;
    const int nw  = NE * HID * DIMD / 4;
    const int nsw = HID * DIMD / 4;
    tohalf_kernel<<<(nx  + 255) / 256, 256>>>(x,   (__half*)xh,  nx);
    tohalf_kernel<<<(nw  + 255) / 256, 256>>>(w1,  (__half*)w1h, nw);
    tohalf_kernel<<<(nw  + 255) / 256, 256>>>(w3,  (__half*)w3h, nw);
    tohalf_kernel<<<(nw  + 255) / 256, 256>>>(w2,  (__half*)w2h, nw);
    tohalf_kernel<<<(nsw + 255) / 256, 256>>>(sw1, (__half*)s1h, nsw);
    tohalf_kernel<<<(nsw + 255) / 256, 256>>>(sw2, (__half*)s2h, nsw);
    tohalf_kernel<<<(nsw + 255) / 256, 256>>>(sw3, (__half*)s3h, nsw);

    gate_kernel<<<T_TOK / 8, 256>>>(x, gw);

    cudaFuncSetAttribute(gemm1_kernel, cudaFuncAttributeMaxDynamicSharedMemorySize, SMEM1);
    cudaFuncSetAttribute(gemm2_kernel, cudaFuncAttributeMaxDynamicSharedMemorySize, SMEM2);

    gemm1_kernel<<<dim3(T_TOK / BM, HID / BN, NE + 1), NT, SMEM1>>>();
    gemm2_kernel<<<dim3(T_TOK / BM, DIMD / BN, NE + 1), NT, SMEM2>>>();
    combine_kernel<<<T_TOK, 256>>>(y);
}